// round 1
// baseline (speedup 1.0000x reference)
#include <cuda_runtime.h>
#include <cuda_bf16.h>

// FFT-based 2x upsample, polyphase formulation. All FFTs are size 4096.
//
//   y[2i+a, 2j+b] = Re( (S_H^a S_W^b x)[i,j] ),  S(u) = IDFT( DFT(u) * w ),
//   w[k] = e^{i pi k / N} * (k < N/2 ? +1 : -1)   (Nyquist -> -i, one-sided)

#define FN    4096
#define LOGN  12
#define TPB   512
#define EPT   (FN / TPB)      // 8
#define FN2   (2 * FN)        // 8192
#define SMEM_BYTES ((size_t)(2 * FN + FN / 2) * sizeof(float2))  // 81920 B

// Scratch: A is 4096x8192 complex (256MB). At is its transpose (256MB).
// Yt (8192x8192 float, 256MB) aliases g_A (A is dead after the transpose).
__device__ __align__(16) float2 g_A[(size_t)FN * FN2];
__device__ __align__(16) float2 g_At[(size_t)FN2 * FN];

__device__ __forceinline__ float2 cmulf(float2 a, float2 b) {
    return make_float2(fmaf(a.x, b.x, -a.y * b.y), fmaf(a.x, b.y, a.y * b.x));
}

// tw[k] = e^{-2 pi i k / FN}, k in [0, FN/2)
__device__ __forceinline__ void fill_tw(float2* tw, int tid) {
    for (int e = tid; e < FN / 2; e += TPB) {
        float sn, cs;
        sincospif(-2.0f * (float)e / (float)FN, &sn, &cs);
        tw[e] = make_float2(cs, sn);
    }
}

// Stockham autosort radix-2 FFT in shared memory. Input in s0 (natural order),
// output in s0 (natural order; LOGN is even so ping-pong returns to s0).
// Caller must __syncthreads() before calling. INV=false: e^{-}, INV=true: e^{+}
// (no 1/N scaling — caller applies it).
template <bool INV>
__device__ void fft_stockham(float2* s0, float2* s1, const float2* tw, int tid) {
    float2* src = s0;
    float2* dst = s1;
    #pragma unroll 1
    for (int stage = 0; stage < LOGN; stage++) {
        int sstr = 1 << stage;
        #pragma unroll
        for (int e = 0; e < EPT / 2; e++) {
            int t = tid + e * TPB;          // t in [0, FN/2)
            int p = t >> stage;
            int q = t & (sstr - 1);
            float2 a = src[t];              // q + sstr*p == t
            float2 b = src[t + FN / 2];     // q + sstr*(p+m), m*sstr == FN/2
            float2 w = tw[p << stage];      // e^{-2 pi i p / n}
            if (INV) w.y = -w.y;
            float2 sum = make_float2(a.x + b.x, a.y + b.y);
            float2 dif = make_float2(a.x - b.x, a.y - b.y);
            int d0 = q + (p << (stage + 1));
            dst[d0] = sum;
            dst[d0 + sstr] = cmulf(dif, w);
        }
        __syncthreads();
        float2* tmp = src; src = dst; dst = tmp;
    }
}

// Multiply spectrum (in s0) by half-sample-shift phase w[k].
__device__ __forceinline__ void halfshift_phase(float2* s0, int tid) {
    #pragma unroll
    for (int e = 0; e < EPT; e++) {
        int k = tid + e * TPB;
        float sn, cs;
        sincospif((float)k / (float)FN, &sn, &cs);   // e^{i pi k / FN}
        float2 w = make_float2(cs, sn);
        if (k >= FN / 2) { w.x = -w.x; w.y = -w.y; }
        s0[k] = cmulf(s0[k], w);
    }
}

// K1: per input row — FFT, phase, IFFT. Write A[i][2j]=(x,0), A[i][2j+1]=shift.
__global__ __launch_bounds__(TPB) void k1_rowpass(const float* __restrict__ x) {
    extern __shared__ float2 sm[];
    float2* s0 = sm;
    float2* s1 = sm + FN;
    float2* tw = sm + 2 * FN;
    int tid = threadIdx.x;
    fill_tw(tw, tid);

    size_t row = blockIdx.x;
    const float* xr = x + row * FN;
    float orig[EPT];
    #pragma unroll
    for (int e = 0; e < EPT; e++) {
        int j = tid + e * TPB;
        float v = xr[j];
        orig[e] = v;
        s0[j] = make_float2(v, 0.0f);
    }
    __syncthreads();

    fft_stockham<false>(s0, s1, tw, tid);
    halfshift_phase(s0, tid);
    __syncthreads();
    fft_stockham<true>(s0, s1, tw, tid);

    const float invN = 1.0f / (float)FN;
    float4* Arow = reinterpret_cast<float4*>(g_A + row * (size_t)FN2);
    #pragma unroll
    for (int e = 0; e < EPT; e++) {
        int j = tid + e * TPB;
        float2 o = s0[j];
        Arow[j] = make_float4(orig[e], 0.0f, o.x * invN, o.y * invN);
    }
}

// K2: complex transpose A[4096][8192] -> At[8192][4096]
__global__ void k2_transpose() {
    __shared__ float2 tile[32][33];
    int tx = threadIdx.x, ty = threadIdx.y;
    int cx = blockIdx.x * 32 + tx;
    int ry = blockIdx.y * 32 + ty;
    #pragma unroll
    for (int j = 0; j < 32; j += 8)
        tile[ty + j][tx] = g_A[(size_t)(ry + j) * FN2 + cx];
    __syncthreads();
    int ox = blockIdx.y * 32 + tx;
    int oy = blockIdx.x * 32 + ty;
    #pragma unroll
    for (int j = 0; j < 32; j += 8)
        g_At[(size_t)(oy + j) * FN + ox] = tile[tx][ty + j];
}

// K3: per At row (= column n of A) — FFT, phase, IFFT.
// Yt[n][2i] = Re(At[n][i]),  Yt[n][2i+1] = Re(shift)/N.
__global__ __launch_bounds__(TPB) void k3_colpass() {
    extern __shared__ float2 sm[];
    float2* s0 = sm;
    float2* s1 = sm + FN;
    float2* tw = sm + 2 * FN;
    int tid = threadIdx.x;
    fill_tw(tw, tid);

    size_t row = blockIdx.x;  // 0..8191
    const float2* ar = g_At + row * (size_t)FN;
    float reo[EPT];
    #pragma unroll
    for (int e = 0; e < EPT; e++) {
        int j = tid + e * TPB;
        float2 v = ar[j];
        reo[e] = v.x;
        s0[j] = v;
    }
    __syncthreads();

    fft_stockham<false>(s0, s1, tw, tid);
    halfshift_phase(s0, tid);
    __syncthreads();
    fft_stockham<true>(s0, s1, tw, tid);

    const float invN = 1.0f / (float)FN;
    float* Yt = reinterpret_cast<float*>(g_A);
    float2* yr = reinterpret_cast<float2*>(Yt + row * (size_t)FN2);
    #pragma unroll
    for (int e = 0; e < EPT; e++) {
        int j = tid + e * TPB;
        yr[j] = make_float2(reo[e], s0[j].x * invN);
    }
}

// K4: float transpose Yt[8192][8192] -> out (out[m][n] = Yt[n][m])
__global__ void k4_transpose(float* __restrict__ out) {
    __shared__ float tile[32][33];
    const float* Yt = reinterpret_cast<const float*>(g_A);
    int tx = threadIdx.x, ty = threadIdx.y;
    int cx = blockIdx.x * 32 + tx;
    int ry = blockIdx.y * 32 + ty;
    #pragma unroll
    for (int j = 0; j < 32; j += 8)
        tile[ty + j][tx] = Yt[(size_t)(ry + j) * FN2 + cx];
    __syncthreads();
    int ox = blockIdx.y * 32 + tx;
    int oy = blockIdx.x * 32 + ty;
    #pragma unroll
    for (int j = 0; j < 32; j += 8)
        out[(size_t)(oy + j) * FN2 + ox] = tile[tx][ty + j];
}

extern "C" void kernel_launch(void* const* d_in, const int* in_sizes, int n_in,
                              void* d_out, int out_size) {
    const float* x = (const float*)d_in[0];
    float* out = (float*)d_out;
    (void)in_sizes; (void)n_in; (void)out_size;

    cudaFuncSetAttribute(k1_rowpass, cudaFuncAttributeMaxDynamicSharedMemorySize,
                         (int)SMEM_BYTES);
    cudaFuncSetAttribute(k3_colpass, cudaFuncAttributeMaxDynamicSharedMemorySize,
                         (int)SMEM_BYTES);

    k1_rowpass<<<FN, TPB, SMEM_BYTES>>>(x);
    k2_transpose<<<dim3(FN2 / 32, FN / 32), dim3(32, 8)>>>();
    k3_colpass<<<FN2, TPB, SMEM_BYTES>>>();
    k4_transpose<<<dim3(FN2 / 32, FN2 / 32), dim3(32, 8)>>>(out);
}

// round 2
// speedup vs baseline: 2.2371x; 2.2371x over previous
#include <cuda_runtime.h>
#include <cuda_bf16.h>

// FFT-based 2x upsample, fully-real polyphase formulation.
//
//   y[2i+a,2j+b] = Re( (S_H^a S_W^b x)[i,j] ),  S(u) = IDFT(DFT(u) * w),
//   w[k] = e^{i pi k/N} * (k < N/2 ? +1 : -1).
//
// For real u:  S(u)[n] = R_u[n] + i*c_u*(-1)^n,  c_u = -u_hat[N/2]/N  (rank-1
// imaginary Nyquist leak). So the whole pipeline runs on REAL data with 2-for-1
// packed complex FFTs (two real rows per complex FFT), plus one global scalar
// correction for the odd-odd quadrant:
//   y[2i+1][2j+1] += (-1)^(i+j) * (-D/N^2),  D = sum_ij x[i][j] (-1)^(i+j).

#define FN    4096
#define TPB   512
#define EPT   (FN / TPB)        // 8 elements/thread
#define NB4   (FN / 4 / TPB)    // 2 radix-4 butterflies/thread/stage
#define NSTG  6                 // 4^6 = 4096
#define NPAIR (FN / 2)          // 2048 row-pairs in K1
#define SMEM_BYTES ((size_t)(2 * FN + FN / 2) * sizeof(float2))  // 80 KB

// pool1 (256MB): B2 [4096x4096 float2] during K1/K2, Yt2 [8192x4096 float2] after.
// pool2 (128MB): Bt2 [4096x4096 float2] (transpose of B2).
__device__ __align__(16) float2 g_pool1[(size_t)8192 * 4096];
__device__ __align__(16) float2 g_pool2[(size_t)4096 * 4096];
__device__ float g_Dpart[NPAIR];
__device__ float g_D[1];

__device__ __forceinline__ float2 cmulf(float2 a, float2 b) {
    return make_float2(fmaf(a.x, b.x, -a.y * b.y), fmaf(a.x, b.y, a.y * b.x));
}
__device__ __forceinline__ float2 cadd(float2 a, float2 b) { return make_float2(a.x + b.x, a.y + b.y); }
__device__ __forceinline__ float2 csub(float2 a, float2 b) { return make_float2(a.x - b.x, a.y - b.y); }

// tw[k] = e^{-2 pi i k / FN}, k in [0, FN/2)
__device__ __forceinline__ void fill_tw(float2* tw, int tid) {
    for (int e = tid; e < FN / 2; e += TPB) {
        float sn, cs;
        sincospif(-2.0f * (float)e / (float)FN, &sn, &cs);
        tw[e] = make_float2(cs, sn);
    }
}

// Stockham autosort radix-4 FFT (6 stages). Natural-order in s0 -> natural-order
// in s0 (even # of ping-pongs). Caller syncs before; each stage syncs after.
// Derived as the exact fusion of two verified radix-2 Stockham stages.
template <bool INV>
__device__ void fft4(float2* s0, float2* s1, const float2* tw, int tid) {
    float2* src = s0;
    float2* dst = s1;
    #pragma unroll 1
    for (int st = 0; st < NSTG; st++) {
        int sstr = 1 << (2 * st);
        #pragma unroll
        for (int e = 0; e < NB4; e++) {
            int t = tid + e * TPB;               // t in [0, FN/4)
            int p = t >> (2 * st);
            int q = t & (sstr - 1);
            float2 x0 = src[t];
            float2 x1 = src[t + FN / 4];
            float2 x2 = src[t + FN / 2];
            float2 x3 = src[t + 3 * FN / 4];
            float2 w1 = tw[p * sstr];            // < FN/4
            float2 w2 = tw[2 * p * sstr];        // < FN/2
            if (INV) { w1.y = -w1.y; w2.y = -w2.y; }
            float2 w3 = cmulf(w1, w2);
            float2 s02 = cadd(x0, x2), d02 = csub(x0, x2);
            float2 s13 = cadd(x1, x3), d13 = csub(x1, x3);
            float2 jd13 = make_float2(-d13.y, d13.x);   // i*d13
            float2 t1 = INV ? cadd(d02, jd13) : csub(d02, jd13);
            float2 t2 = csub(s02, s13);
            float2 t3 = INV ? csub(d02, jd13) : cadd(d02, jd13);
            int base = q + 4 * sstr * p;
            dst[base]            = cadd(s02, s13);
            dst[base + sstr]     = cmulf(t1, w1);
            dst[base + 2 * sstr] = cmulf(t2, w2);
            dst[base + 3 * sstr] = cmulf(t3, w3);
        }
        __syncthreads();
        float2* tmp = src; src = dst; dst = tmp;
    }
}

// Multiply spectrum in s0 by half-sample-shift phase w[k].
__device__ __forceinline__ void halfshift_phase(float2* s0, int tid) {
    #pragma unroll
    for (int e = 0; e < EPT; e++) {
        int k = tid + e * TPB;
        float sn, cs;
        sincospif((float)k / (float)FN, &sn, &cs);
        float2 w = make_float2(cs, sn);
        if (k >= FN / 2) { w.x = -w.x; w.y = -w.y; }
        s0[k] = cmulf(s0[k], w);
    }
}

// K1: 2-for-1 row pass. Block r handles rows 2r, 2r+1.
// z = u + i v; S(z) = S(u)+i S(v); unmix with zny = z_hat[N/2]:
//   R_u[n] = (Re S(z)[n]*N_unscaled - (-1)^n * zny.y)/N
//   R_v[n] = (Im ... + (-1)^n * zny.x)/N
// B2[i][j] = (x[i][j], R_i[j])  (even col, odd col interleaved as float2).
__global__ __launch_bounds__(TPB) void k1_rowpass(const float* __restrict__ x) {
    extern __shared__ float2 sm[];
    float2* s0 = sm;
    float2* s1 = sm + FN;
    float2* tw = sm + 2 * FN;
    int tid = threadIdx.x;
    fill_tw(tw, tid);

    size_t r = blockIdx.x;
    const float* u = x + (2 * r) * (size_t)FN;
    const float* v = u + FN;
    float2 z[EPT];
    #pragma unroll
    for (int e = 0; e < EPT; e++) {
        int j = tid + e * TPB;
        z[e] = make_float2(u[j], v[j]);
        s0[j] = z[e];
    }
    __syncthreads();

    fft4<false>(s0, s1, tw, tid);
    float2 zny = s0[FN / 2];              // broadcast read (synced)
    halfshift_phase(s0, tid);
    __syncthreads();
    fft4<true>(s0, s1, tw, tid);

    if (tid == 0) g_Dpart[r] = zny.x - zny.y;   // (+1)*u_ny + (-1)*v_ny

    const float invN = 1.0f / (float)FN;
    float sgn = (tid & 1) ? -1.0f : 1.0f;       // (-1)^j, j parity == tid parity
    float2* row0 = g_pool1 + (2 * r) * (size_t)FN;
    float2* row1 = row0 + FN;
    #pragma unroll
    for (int e = 0; e < EPT; e++) {
        int j = tid + e * TPB;
        float2 o = s0[j];
        float Ru = (o.x - sgn * zny.y) * invN;
        float Rv = (o.y + sgn * zny.x) * invN;
        row0[j] = make_float2(z[e].x, Ru);
        row1[j] = make_float2(z[e].y, Rv);
    }
}

// Deterministic reduction of g_Dpart -> g_D.
__global__ void k_reduce() {
    __shared__ float sh[TPB];
    float s = 0.0f;
    for (int i = threadIdx.x; i < NPAIR; i += TPB) s += g_Dpart[i];
    sh[threadIdx.x] = s;
    __syncthreads();
    for (int o = TPB / 2; o > 0; o >>= 1) {
        if (threadIdx.x < o) sh[threadIdx.x] += sh[threadIdx.x + o];
        __syncthreads();
    }
    if (threadIdx.x == 0) g_D[0] = sh[0];
}

// K2: transpose B2 [4096x4096 float2] -> Bt2 (pool2).
// Bt2[c][i] = (B[i][2c], B[i][2c+1]) = packed complex input for K3 block c.
__global__ void k2_transpose() {
    __shared__ float2 tile[32][33];
    int tx = threadIdx.x, ty = threadIdx.y;
    int cx = blockIdx.x * 32 + tx;
    int ry = blockIdx.y * 32 + ty;
    #pragma unroll
    for (int j = 0; j < 32; j += 8)
        tile[ty + j][tx] = g_pool1[(size_t)(ry + j) * FN + cx];
    __syncthreads();
    int ox = blockIdx.y * 32 + tx;
    int oy = blockIdx.x * 32 + ty;
    #pragma unroll
    for (int j = 0; j < 32; j += 8)
        g_pool2[(size_t)(oy + j) * FN + ox] = tile[tx][ty + j];
}

// K3: 2-for-1 column pass. Block c handles output columns 2c (even) and 2c+1 (odd).
// z[i] = Bt2[c][i] = (x-col value, R-col value). After unmix:
//   Yt2[2c  ][i] = (y[2i][2c],   y[2i+1][2c]  ) = (z.x, Ru)
//   Yt2[2c+1][i] = (y[2i][2c+1], y[2i+1][2c+1]) = (z.y, Rv + (-1)^(i+c)*corr)
__global__ __launch_bounds__(TPB) void k3_colpass() {
    extern __shared__ float2 sm[];
    float2* s0 = sm;
    float2* s1 = sm + FN;
    float2* tw = sm + 2 * FN;
    int tid = threadIdx.x;
    fill_tw(tw, tid);

    size_t c = blockIdx.x;
    const float2* bt = g_pool2 + c * (size_t)FN;
    float2 z[EPT];
    #pragma unroll
    for (int e = 0; e < EPT; e++) {
        int j = tid + e * TPB;
        z[e] = bt[j];
        s0[j] = z[e];
    }
    __syncthreads();

    fft4<false>(s0, s1, tw, tid);
    float2 zny = s0[FN / 2];
    halfshift_phase(s0, tid);
    __syncthreads();
    fft4<true>(s0, s1, tw, tid);

    const float invN = 1.0f / (float)FN;
    float corr = -g_D[0] * invN * invN;          // -D/N^2
    float sgnc = (c & 1) ? -corr : corr;         // (-1)^c * corr
    float sgn = (tid & 1) ? -1.0f : 1.0f;        // (-1)^i
    float2* y0 = g_pool1 + (2 * c) * (size_t)FN; // Yt2 rows (aliases dead B2)
    float2* y1 = y0 + FN;
    #pragma unroll
    for (int e = 0; e < EPT; e++) {
        int j = tid + e * TPB;
        float2 o = s0[j];
        float Ru = (o.x - sgn * zny.y) * invN;
        float Rv = (o.y + sgn * zny.x) * invN;
        y0[j] = make_float2(z[e].x, Ru);
        y1[j] = make_float2(z[e].y, Rv + sgn * sgnc);
    }
}

// K4: transpose Yt2 [8192(col) x 4096(i) float2] -> out [8192 x 8192 floats].
// out[2i+0][col] = Yt2[col][i].x, out[2i+1][col] = Yt2[col][i].y.
__global__ void k4_transpose(float* __restrict__ out) {
    __shared__ float2 tile[32][33];
    int tx = threadIdx.x, ty = threadIdx.y;
    int ib = blockIdx.x * 32;
    int cb = blockIdx.y * 32;
    #pragma unroll
    for (int j = 0; j < 32; j += 8)
        tile[ty + j][tx] = g_pool1[(size_t)(cb + ty + j) * FN + ib + tx];
    __syncthreads();
    #pragma unroll
    for (int j = 0; j < 32; j += 8) {
        float2 v = tile[tx][ty + j];
        size_t rr = 2 * (size_t)(ib + ty + j);
        out[rr * 8192 + cb + tx] = v.x;
        out[(rr + 1) * 8192 + cb + tx] = v.y;
    }
}

extern "C" void kernel_launch(void* const* d_in, const int* in_sizes, int n_in,
                              void* d_out, int out_size) {
    const float* x = (const float*)d_in[0];
    float* out = (float*)d_out;
    (void)in_sizes; (void)n_in; (void)out_size;

    cudaFuncSetAttribute(k1_rowpass, cudaFuncAttributeMaxDynamicSharedMemorySize,
                         (int)SMEM_BYTES);
    cudaFuncSetAttribute(k3_colpass, cudaFuncAttributeMaxDynamicSharedMemorySize,
                         (int)SMEM_BYTES);

    k1_rowpass<<<NPAIR, TPB, SMEM_BYTES>>>(x);
    k_reduce<<<1, TPB>>>();
    k2_transpose<<<dim3(FN / 32, FN / 32), dim3(32, 8)>>>();
    k3_colpass<<<FN, TPB, SMEM_BYTES>>>();
    k4_transpose<<<dim3(FN / 32, 8192 / 32), dim3(32, 8)>>>(out);
}

// round 3
// speedup vs baseline: 3.2589x; 1.4568x over previous
#include <cuda_runtime.h>
#include <cuda_bf16.h>

// FFT-based 2x upsample, fully-real polyphase formulation (see R2).
// This round: register-resident radix-8 four-step FFT (4096 = 8^4), 3 shared
// exchanges per FFT, bank-conflict-free via a GF(2) address swizzle. Phase
// multiply + Nyquist capture happen in registers between fwd and inv FFT.

#define FN    4096
#define TPB   512
#define NPAIR (FN / 2)

// pool1 (256MB): B2 [4096x4096 float2] during K1/K2, Yt2 [8192x4096 float2] after.
// pool2 (128MB): Bt2 [4096x4096 float2].
__device__ __align__(16) float2 g_pool1[(size_t)8192 * 4096];
__device__ __align__(16) float2 g_pool2[(size_t)4096 * 4096];
__device__ float g_Dpart[NPAIR];
__device__ float g_D[1];

__device__ __forceinline__ float2 cmul(float2 a, float2 b) {
    return make_float2(fmaf(a.x, b.x, -a.y * b.y), fmaf(a.x, b.y, a.y * b.x));
}
__device__ __forceinline__ float2 cadd(float2 a, float2 b) { return make_float2(a.x + b.x, a.y + b.y); }
__device__ __forceinline__ float2 csub(float2 a, float2 b) { return make_float2(a.x - b.x, a.y - b.y); }

// Bank swizzle: bits 4,5,6 XORed into bank bits so that every exchange pattern
// (varying bits {0..3}, {0,1,2,6}, {3,4,5,6} per half-warp) maps injectively
// onto the 16 8-byte bank-pairs. Bijective on [0,4096).
__device__ __forceinline__ int SW(int a) {
    return a ^ ((a >> 2) & 4) ^ ((a >> 4) & 2) ^ (((a >> 6) & 1) * 9);
}

// e^{i*pi*t}
__device__ __forceinline__ float2 expi(float t) {
    float2 w; sincospif(t, &w.y, &w.x); return w;
}

// Radix-8 DFT butterfly. FWD (INV=false): W_8 = e^{-2pi i/8}; INV: conjugate.
template <bool INV>
__device__ __forceinline__ void bfly8(const float2 x[8], float2 y[8]) {
    float2 a0 = cadd(x[0], x[4]), a1 = csub(x[0], x[4]);
    float2 a2 = cadd(x[2], x[6]), a3 = csub(x[2], x[6]);
    float2 a4 = cadd(x[1], x[5]), a5 = csub(x[1], x[5]);
    float2 a6 = cadd(x[3], x[7]), a7 = csub(x[3], x[7]);
    float2 b0 = cadd(a0, a2), b1 = csub(a0, a2);
    float2 b2 = cadd(a4, a6), b3 = csub(a4, a6);
    // mul by -i (fwd) / +i (inv)
    float2 c3  = INV ? make_float2(-a3.y, a3.x) : make_float2(a3.y, -a3.x);
    float2 c7  = INV ? make_float2(-a7.y, a7.x) : make_float2(a7.y, -a7.x);
    float2 jb3 = INV ? make_float2(-b3.y, b3.x) : make_float2(b3.y, -b3.x);
    float2 e1 = cadd(a1, c3), e3 = csub(a1, c3);
    float2 f5 = cadd(a5, c7), f7 = csub(a5, c7);
    const float s = 0.70710678118654752440f;
    float2 W1 = INV ? make_float2(s, s)  : make_float2(s, -s);
    float2 W3 = INV ? make_float2(-s, s) : make_float2(-s, -s);
    float2 g5 = cmul(W1, f5), g7 = cmul(W3, f7);
    y[0] = cadd(b0, b2); y[4] = csub(b0, b2);
    y[2] = cadd(b1, jb3); y[6] = csub(b1, jb3);
    y[1] = cadd(e1, g5); y[5] = csub(e1, g5);
    y[3] = cadd(e3, g7); y[7] = csub(e3, g7);
}

// y[k] *= w^k, k=1..7 (twiddle chain)
__device__ __forceinline__ void twapply(float2 y[8], float2 w) {
    float2 wk = w;
    y[1] = cmul(y[1], wk);
    #pragma unroll
    for (int k = 2; k < 8; k++) { wk = cmul(wk, w); y[k] = cmul(y[k], wk); }
}

// S-transform: z[n3] = data[tid + 512*n3] (complex, packed pair of real rows).
// Computes z <- N * IDFT( DFT(z) * halfshift_w ), zny_out <- DFT(z)[2048].
// buf must be float2[4097] shared.
__device__ __forceinline__ void stransform(float2 z[8], float2* buf, int tid,
                                           float2* zny_out) {
    const int k0 = tid >> 6;
    const int s6 = tid & 63;
    const int k1 = (tid >> 3) & 7;
    const int n0 = tid & 7;
    const int m  = (tid >> 6) + 8 * ((tid >> 3) & 7) + 64 * (tid & 7);
    float2 y[8], t[8];

    // ---- forward FFT (DIF four-step, output digit k = k0+8k1+64k2+512k3) ----
    bfly8<false>(z, y);                         // over n3 (stride 512)
    twapply(y, expi(-(float)tid / 2048.0f));    // W_4096^{r k0}
    #pragma unroll
    for (int q = 0; q < 8; q++) buf[SW(512 * q + tid)] = y[q];
    __syncthreads();
    #pragma unroll
    for (int q = 0; q < 8; q++) t[q] = buf[SW(512 * k0 + 64 * q + s6)];
    __syncthreads();

    bfly8<false>(t, y);                         // over n2 (stride 64)
    twapply(y, expi(-(float)s6 / 256.0f));      // W_512^{s k1}
    #pragma unroll
    for (int q = 0; q < 8; q++) buf[SW(512 * k0 + 64 * q + s6)] = y[q];
    __syncthreads();
    #pragma unroll
    for (int q = 0; q < 8; q++) t[q] = buf[SW(512 * k0 + 64 * k1 + 8 * q + n0)];
    __syncthreads();

    bfly8<false>(t, y);                         // over n1 (stride 8)
    twapply(y, expi(-(float)n0 / 32.0f));       // W_64^{n0 k2}
    #pragma unroll
    for (int q = 0; q < 8; q++) buf[SW(512 * k0 + 64 * k1 + 8 * q + n0)] = y[q];
    __syncthreads();
    #pragma unroll
    for (int q = 0; q < 8; q++) t[q] = buf[SW(8 * tid + q)];
    __syncthreads();

    bfly8<false>(t, y);                         // over n0 -> X[m + 512 j]

    // zny = X[2048] (m=0, j=4) lives on thread 0
    if (tid == 0) buf[4096] = y[4];

    // ---- half-sample-shift phase, in registers ----
    // w[k] = e^{i pi k/4096} * (k<2048 ? +1 : -1), k = m + 512 j
    {
        float2 wm = expi((float)m / 4096.0f);
        const float2 EJ[8] = {
            { 1.0f, 0.0f},
            { 0.92387953251128675613f,  0.38268343236508977173f},
            { 0.70710678118654752440f,  0.70710678118654752440f},
            { 0.38268343236508977173f,  0.92387953251128675613f},
            { 0.0f, -1.0f},
            { 0.38268343236508977173f, -0.92387953251128675613f},
            { 0.70710678118654752440f, -0.70710678118654752440f},
            { 0.92387953251128675613f, -0.38268343236508977173f}};
        #pragma unroll
        for (int j = 0; j < 8; j++) y[j] = cmul(y[j], cmul(wm, EJ[j]));
    }

    // ---- inverse FFT (mirror stages, conjugate twiddles) ----
    bfly8<true>(y, t);                          // over k3
    #pragma unroll
    for (int q = 0; q < 8; q++) buf[SW(8 * tid + q)] = t[q];
    __syncthreads();
    #pragma unroll
    for (int q = 0; q < 8; q++) t[q] = buf[SW(512 * k0 + 64 * k1 + 8 * q + n0)];
    __syncthreads();

    twapply(t, expi((float)n0 / 32.0f));        // conj W_64^{n0 k2}
    bfly8<true>(t, y);                          // over k2 -> s = n0 + 8 n1
    #pragma unroll
    for (int q = 0; q < 8; q++) buf[SW(512 * k0 + 64 * k1 + 8 * q + n0)] = y[q];
    __syncthreads();
    #pragma unroll
    for (int q = 0; q < 8; q++) t[q] = buf[SW(512 * k0 + 64 * q + s6)];
    __syncthreads();

    twapply(t, expi((float)s6 / 256.0f));       // conj W_512^{s k1}
    bfly8<true>(t, y);                          // over k1 -> r = s + 64 n2
    #pragma unroll
    for (int q = 0; q < 8; q++) buf[SW(512 * k0 + 64 * q + s6)] = y[q];
    __syncthreads();
    #pragma unroll
    for (int q = 0; q < 8; q++) t[q] = buf[SW(512 * q + tid)];

    twapply(t, expi((float)tid / 2048.0f));     // conj W_4096^{r k0}
    bfly8<true>(t, z);                          // over k0 -> z[n3] = N*S[tid+512 n3]

    *zny_out = buf[4096];                       // written >= 3 syncs ago
}

// K1: 2-for-1 row pass (block r handles input rows 2r, 2r+1).
__global__ __launch_bounds__(TPB) void k1_rowpass(const float* __restrict__ x) {
    __shared__ float2 buf[4097];
    int tid = threadIdx.x;
    size_t r = blockIdx.x;
    const float* u = x + (2 * r) * (size_t)FN;
    const float* v = u + FN;
    float2 z[8], z0[8];
    #pragma unroll
    for (int e = 0; e < 8; e++) {
        int j = tid + e * TPB;
        z[e] = make_float2(u[j], v[j]);
        z0[e] = z[e];
    }
    float2 zny;
    stransform(z, buf, tid, &zny);
    if (tid == 0) g_Dpart[r] = zny.x - zny.y;

    const float invN = 1.0f / 4096.0f;
    float sgn = (tid & 1) ? -1.0f : 1.0f;       // (-1)^j
    float2* row0 = g_pool1 + (2 * r) * (size_t)FN;
    float2* row1 = row0 + FN;
    #pragma unroll
    for (int e = 0; e < 8; e++) {
        int j = tid + e * TPB;
        float Ru = (z[e].x - sgn * zny.y) * invN;
        float Rv = (z[e].y + sgn * zny.x) * invN;
        row0[j] = make_float2(z0[e].x, Ru);
        row1[j] = make_float2(z0[e].y, Rv);
    }
}

// Deterministic reduction of g_Dpart -> g_D.
__global__ void k_reduce() {
    __shared__ float sh[TPB];
    float s = 0.0f;
    for (int i = threadIdx.x; i < NPAIR; i += TPB) s += g_Dpart[i];
    sh[threadIdx.x] = s;
    __syncthreads();
    for (int o = TPB / 2; o > 0; o >>= 1) {
        if (threadIdx.x < o) sh[threadIdx.x] += sh[threadIdx.x + o];
        __syncthreads();
    }
    if (threadIdx.x == 0) g_D[0] = sh[0];
}

// K2: transpose B2 [4096x4096 float2] -> Bt2 (pool2).
__global__ void k2_transpose() {
    __shared__ float2 tile[32][33];
    int tx = threadIdx.x, ty = threadIdx.y;
    int cx = blockIdx.x * 32 + tx;
    int ry = blockIdx.y * 32 + ty;
    #pragma unroll
    for (int j = 0; j < 32; j += 8)
        tile[ty + j][tx] = g_pool1[(size_t)(ry + j) * FN + cx];
    __syncthreads();
    int ox = blockIdx.y * 32 + tx;
    int oy = blockIdx.x * 32 + ty;
    #pragma unroll
    for (int j = 0; j < 32; j += 8)
        g_pool2[(size_t)(oy + j) * FN + ox] = tile[tx][ty + j];
}

// K3: 2-for-1 column pass (block c handles output columns 2c, 2c+1).
__global__ __launch_bounds__(TPB) void k3_colpass() {
    __shared__ float2 buf[4097];
    int tid = threadIdx.x;
    size_t c = blockIdx.x;
    const float2* bt = g_pool2 + c * (size_t)FN;
    float2 z[8], z0[8];
    #pragma unroll
    for (int e = 0; e < 8; e++) {
        int j = tid + e * TPB;
        z[e] = bt[j];
        z0[e] = z[e];
    }
    float2 zny;
    stransform(z, buf, tid, &zny);

    const float invN = 1.0f / 4096.0f;
    float corr = -g_D[0] * invN * invN;         // -D/N^2
    float sgnc = (c & 1) ? -corr : corr;        // (-1)^c * corr
    float sgn = (tid & 1) ? -1.0f : 1.0f;       // (-1)^i
    float2* y0 = g_pool1 + (2 * c) * (size_t)FN;
    float2* y1 = y0 + FN;
    #pragma unroll
    for (int e = 0; e < 8; e++) {
        int j = tid + e * TPB;
        float Ru = (z[e].x - sgn * zny.y) * invN;
        float Rv = (z[e].y + sgn * zny.x) * invN;
        y0[j] = make_float2(z0[e].x, Ru);
        y1[j] = make_float2(z0[e].y, Rv + sgn * sgnc);
    }
}

// K4: transpose Yt2 [8192(col) x 4096(i) float2] -> out [8192 x 8192 floats].
__global__ void k4_transpose(float* __restrict__ out) {
    __shared__ float2 tile[32][33];
    int tx = threadIdx.x, ty = threadIdx.y;
    int ib = blockIdx.x * 32;
    int cb = blockIdx.y * 32;
    #pragma unroll
    for (int j = 0; j < 32; j += 8)
        tile[ty + j][tx] = g_pool1[(size_t)(cb + ty + j) * FN + ib + tx];
    __syncthreads();
    #pragma unroll
    for (int j = 0; j < 32; j += 8) {
        float2 v = tile[tx][ty + j];
        size_t rr = 2 * (size_t)(ib + ty + j);
        out[rr * 8192 + cb + tx] = v.x;
        out[(rr + 1) * 8192 + cb + tx] = v.y;
    }
}

extern "C" void kernel_launch(void* const* d_in, const int* in_sizes, int n_in,
                              void* d_out, int out_size) {
    const float* x = (const float*)d_in[0];
    float* out = (float*)d_out;
    (void)in_sizes; (void)n_in; (void)out_size;

    k1_rowpass<<<NPAIR, TPB>>>(x);
    k_reduce<<<1, TPB>>>();
    k2_transpose<<<dim3(FN / 32, FN / 32), dim3(32, 8)>>>();
    k3_colpass<<<FN, TPB>>>();
    k4_transpose<<<dim3(FN / 32, 8192 / 32), dim3(32, 8)>>>(out);
}

// round 4
// speedup vs baseline: 3.3080x; 1.0151x over previous
#include <cuda_runtime.h>
#include <cuda_bf16.h>

// FFT-based 2x upsample, fully-real polyphase formulation (see R2/R3).
// R4: all twiddles come from two 4KB global tables (L1-resident) filled by an
// init kernel — zero MUFU in the FFT kernels. Inverse twiddles are register
// conjugates of the forward bases.

#define FN    4096
#define TPB   512
#define NPAIR (FN / 2)

// pool1 (256MB): B2 [4096x4096 float2] during K1/K2, Yt2 [8192x4096 float2] after.
// pool2 (128MB): Bt2 [4096x4096 float2].
__device__ __align__(16) float2 g_pool1[(size_t)8192 * 4096];
__device__ __align__(16) float2 g_pool2[(size_t)4096 * 4096];
__device__ float g_Dpart[NPAIR];
__device__ float g_D[1];
// twA[k] = e^{-2 pi i k/4096}, twB[k] = e^{+i pi k/4096}, k < 512
__device__ __align__(16) float2 g_twA[512];
__device__ __align__(16) float2 g_twB[512];

__device__ __forceinline__ float2 cmul(float2 a, float2 b) {
    return make_float2(fmaf(a.x, b.x, -a.y * b.y), fmaf(a.x, b.y, a.y * b.x));
}
__device__ __forceinline__ float2 cadd(float2 a, float2 b) { return make_float2(a.x + b.x, a.y + b.y); }
__device__ __forceinline__ float2 csub(float2 a, float2 b) { return make_float2(a.x - b.x, a.y - b.y); }
__device__ __forceinline__ float2 cconj(float2 a) { return make_float2(a.x, -a.y); }

// Bank swizzle (see R3): bijective on [0,4096), conflict-free for all six
// exchange patterns (varying bits {0..3}, {0,1,2,6}, {3,4,5,6} per half-warp).
__device__ __forceinline__ int SW(int a) {
    return a ^ ((a >> 2) & 4) ^ ((a >> 4) & 2) ^ (((a >> 6) & 1) * 9);
}

__global__ void k0_twiddle() {
    int k = threadIdx.x;           // 0..511
    float sn, cs;
    sincospif(-(float)k / 2048.0f, &sn, &cs);   // e^{-2 pi i k/4096}
    g_twA[k] = make_float2(cs, sn);
    sincospif((float)k / 4096.0f, &sn, &cs);    // e^{+i pi k/4096}
    g_twB[k] = make_float2(cs, sn);
}

// Radix-8 DFT butterfly. FWD: W_8 = e^{-2pi i/8}; INV: conjugate.
template <bool INV>
__device__ __forceinline__ void bfly8(const float2 x[8], float2 y[8]) {
    float2 a0 = cadd(x[0], x[4]), a1 = csub(x[0], x[4]);
    float2 a2 = cadd(x[2], x[6]), a3 = csub(x[2], x[6]);
    float2 a4 = cadd(x[1], x[5]), a5 = csub(x[1], x[5]);
    float2 a6 = cadd(x[3], x[7]), a7 = csub(x[3], x[7]);
    float2 b0 = cadd(a0, a2), b1 = csub(a0, a2);
    float2 b2 = cadd(a4, a6), b3 = csub(a4, a6);
    float2 c3  = INV ? make_float2(-a3.y, a3.x) : make_float2(a3.y, -a3.x);
    float2 c7  = INV ? make_float2(-a7.y, a7.x) : make_float2(a7.y, -a7.x);
    float2 jb3 = INV ? make_float2(-b3.y, b3.x) : make_float2(b3.y, -b3.x);
    float2 e1 = cadd(a1, c3), e3 = csub(a1, c3);
    float2 f5 = cadd(a5, c7), f7 = csub(a5, c7);
    const float s = 0.70710678118654752440f;
    float2 W1 = INV ? make_float2(s, s)  : make_float2(s, -s);
    float2 W3 = INV ? make_float2(-s, s) : make_float2(-s, -s);
    float2 g5 = cmul(W1, f5), g7 = cmul(W3, f7);
    y[0] = cadd(b0, b2); y[4] = csub(b0, b2);
    y[2] = cadd(b1, jb3); y[6] = csub(b1, jb3);
    y[1] = cadd(e1, g5); y[5] = csub(e1, g5);
    y[3] = cadd(e3, g7); y[7] = csub(e3, g7);
}

// y[k] *= w^k, k=1..7 (twiddle chain)
__device__ __forceinline__ void twapply(float2 y[8], float2 w) {
    float2 wk = w;
    y[1] = cmul(y[1], wk);
    #pragma unroll
    for (int k = 2; k < 8; k++) { wk = cmul(wk, w); y[k] = cmul(y[k], wk); }
}

// S-transform (see R3): z <- N * IDFT( DFT(z) * halfshift_w ), zny <- DFT(z)[2048].
__device__ __forceinline__ void stransform(float2 z[8], float2* buf, int tid,
                                           float2* zny_out) {
    const int k0 = tid >> 6;
    const int s6 = tid & 63;
    const int k1 = (tid >> 3) & 7;
    const int n0 = tid & 7;
    const int m  = (tid >> 6) + 8 * ((tid >> 3) & 7) + 64 * (tid & 7);
    float2 y[8], t[8];

    // twiddle bases from tables (all indices < 512, L1-hit LDG)
    const float2 w1b = __ldg(&g_twA[tid]);       // e^{-i pi tid/2048}
    const float2 w2b = __ldg(&g_twA[8 * s6]);    // e^{-i pi s6/256}
    const float2 w3b = __ldg(&g_twA[64 * n0]);   // e^{-i pi n0/32}
    const float2 wm  = __ldg(&g_twB[m]);         // e^{+i pi m/4096}

    // ---- forward FFT (DIF four-step) ----
    bfly8<false>(z, y);
    twapply(y, w1b);
    #pragma unroll
    for (int q = 0; q < 8; q++) buf[SW(512 * q + tid)] = y[q];
    __syncthreads();
    #pragma unroll
    for (int q = 0; q < 8; q++) t[q] = buf[SW(512 * k0 + 64 * q + s6)];
    __syncthreads();

    bfly8<false>(t, y);
    twapply(y, w2b);
    #pragma unroll
    for (int q = 0; q < 8; q++) buf[SW(512 * k0 + 64 * q + s6)] = y[q];
    __syncthreads();
    #pragma unroll
    for (int q = 0; q < 8; q++) t[q] = buf[SW(512 * k0 + 64 * k1 + 8 * q + n0)];
    __syncthreads();

    bfly8<false>(t, y);
    twapply(y, w3b);
    #pragma unroll
    for (int q = 0; q < 8; q++) buf[SW(512 * k0 + 64 * k1 + 8 * q + n0)] = y[q];
    __syncthreads();
    #pragma unroll
    for (int q = 0; q < 8; q++) t[q] = buf[SW(8 * tid + q)];
    __syncthreads();

    bfly8<false>(t, y);                         // -> X[m + 512 j]

    if (tid == 0) buf[4096] = y[4];             // zny = X[2048]

    // ---- half-sample-shift phase (registers) ----
    {
        const float2 EJ[8] = {
            { 1.0f, 0.0f},
            { 0.92387953251128675613f,  0.38268343236508977173f},
            { 0.70710678118654752440f,  0.70710678118654752440f},
            { 0.38268343236508977173f,  0.92387953251128675613f},
            { 0.0f, -1.0f},
            { 0.38268343236508977173f, -0.92387953251128675613f},
            { 0.70710678118654752440f, -0.70710678118654752440f},
            { 0.92387953251128675613f, -0.38268343236508977173f}};
        #pragma unroll
        for (int j = 0; j < 8; j++) y[j] = cmul(y[j], cmul(wm, EJ[j]));
    }

    // ---- inverse FFT (mirror stages, conjugate bases) ----
    bfly8<true>(y, t);
    #pragma unroll
    for (int q = 0; q < 8; q++) buf[SW(8 * tid + q)] = t[q];
    __syncthreads();
    #pragma unroll
    for (int q = 0; q < 8; q++) t[q] = buf[SW(512 * k0 + 64 * k1 + 8 * q + n0)];
    __syncthreads();

    twapply(t, cconj(w3b));
    bfly8<true>(t, y);
    #pragma unroll
    for (int q = 0; q < 8; q++) buf[SW(512 * k0 + 64 * k1 + 8 * q + n0)] = y[q];
    __syncthreads();
    #pragma unroll
    for (int q = 0; q < 8; q++) t[q] = buf[SW(512 * k0 + 64 * q + s6)];
    __syncthreads();

    twapply(t, cconj(w2b));
    bfly8<true>(t, y);
    #pragma unroll
    for (int q = 0; q < 8; q++) buf[SW(512 * k0 + 64 * q + s6)] = y[q];
    __syncthreads();
    #pragma unroll
    for (int q = 0; q < 8; q++) t[q] = buf[SW(512 * q + tid)];

    twapply(t, cconj(w1b));
    bfly8<true>(t, z);                          // z[n3] = N*S[tid+512 n3]

    *zny_out = buf[4096];                       // written >= 3 syncs ago
}

// K1: 2-for-1 row pass (block r handles input rows 2r, 2r+1).
__global__ __launch_bounds__(TPB) void k1_rowpass(const float* __restrict__ x) {
    __shared__ float2 buf[4097];
    int tid = threadIdx.x;
    size_t r = blockIdx.x;
    const float* u = x + (2 * r) * (size_t)FN;
    const float* v = u + FN;
    float2 z[8], z0[8];
    #pragma unroll
    for (int e = 0; e < 8; e++) {
        int j = tid + e * TPB;
        z[e] = make_float2(u[j], v[j]);
        z0[e] = z[e];
    }
    float2 zny;
    stransform(z, buf, tid, &zny);
    if (tid == 0) g_Dpart[r] = zny.x - zny.y;

    const float invN = 1.0f / 4096.0f;
    float sgn = (tid & 1) ? -1.0f : 1.0f;       // (-1)^j
    float2* row0 = g_pool1 + (2 * r) * (size_t)FN;
    float2* row1 = row0 + FN;
    #pragma unroll
    for (int e = 0; e < 8; e++) {
        int j = tid + e * TPB;
        float Ru = (z[e].x - sgn * zny.y) * invN;
        float Rv = (z[e].y + sgn * zny.x) * invN;
        row0[j] = make_float2(z0[e].x, Ru);
        row1[j] = make_float2(z0[e].y, Rv);
    }
}

// Deterministic reduction of g_Dpart -> g_D.
__global__ void k_reduce() {
    __shared__ float sh[TPB];
    float s = 0.0f;
    for (int i = threadIdx.x; i < NPAIR; i += TPB) s += g_Dpart[i];
    sh[threadIdx.x] = s;
    __syncthreads();
    for (int o = TPB / 2; o > 0; o >>= 1) {
        if (threadIdx.x < o) sh[threadIdx.x] += sh[threadIdx.x + o];
        __syncthreads();
    }
    if (threadIdx.x == 0) g_D[0] = sh[0];
}

// K2: transpose B2 [4096x4096 float2] -> Bt2 (pool2).
__global__ void k2_transpose() {
    __shared__ float2 tile[32][33];
    int tx = threadIdx.x, ty = threadIdx.y;
    int cx = blockIdx.x * 32 + tx;
    int ry = blockIdx.y * 32 + ty;
    #pragma unroll
    for (int j = 0; j < 32; j += 8)
        tile[ty + j][tx] = g_pool1[(size_t)(ry + j) * FN + cx];
    __syncthreads();
    int ox = blockIdx.y * 32 + tx;
    int oy = blockIdx.x * 32 + ty;
    #pragma unroll
    for (int j = 0; j < 32; j += 8)
        g_pool2[(size_t)(oy + j) * FN + ox] = tile[tx][ty + j];
}

// K3: 2-for-1 column pass (block c handles output columns 2c, 2c+1).
__global__ __launch_bounds__(TPB) void k3_colpass() {
    __shared__ float2 buf[4097];
    int tid = threadIdx.x;
    size_t c = blockIdx.x;
    const float2* bt = g_pool2 + c * (size_t)FN;
    float2 z[8], z0[8];
    #pragma unroll
    for (int e = 0; e < 8; e++) {
        int j = tid + e * TPB;
        z[e] = bt[j];
        z0[e] = z[e];
    }
    float2 zny;
    stransform(z, buf, tid, &zny);

    const float invN = 1.0f / 4096.0f;
    float corr = -g_D[0] * invN * invN;         // -D/N^2
    float sgnc = (c & 1) ? -corr : corr;        // (-1)^c * corr
    float sgn = (tid & 1) ? -1.0f : 1.0f;       // (-1)^i
    float2* y0 = g_pool1 + (2 * c) * (size_t)FN;
    float2* y1 = y0 + FN;
    #pragma unroll
    for (int e = 0; e < 8; e++) {
        int j = tid + e * TPB;
        float Ru = (z[e].x - sgn * zny.y) * invN;
        float Rv = (z[e].y + sgn * zny.x) * invN;
        y0[j] = make_float2(z0[e].x, Ru);
        y1[j] = make_float2(z0[e].y, Rv + sgn * sgnc);
    }
}

// K4: transpose Yt2 [8192(col) x 4096(i) float2] -> out [8192 x 8192 floats].
__global__ void k4_transpose(float* __restrict__ out) {
    __shared__ float2 tile[32][33];
    int tx = threadIdx.x, ty = threadIdx.y;
    int ib = blockIdx.x * 32;
    int cb = blockIdx.y * 32;
    #pragma unroll
    for (int j = 0; j < 32; j += 8)
        tile[ty + j][tx] = g_pool1[(size_t)(cb + ty + j) * FN + ib + tx];
    __syncthreads();
    #pragma unroll
    for (int j = 0; j < 32; j += 8) {
        float2 v = tile[tx][ty + j];
        size_t rr = 2 * (size_t)(ib + ty + j);
        out[rr * 8192 + cb + tx] = v.x;
        out[(rr + 1) * 8192 + cb + tx] = v.y;
    }
}

extern "C" void kernel_launch(void* const* d_in, const int* in_sizes, int n_in,
                              void* d_out, int out_size) {
    const float* x = (const float*)d_in[0];
    float* out = (float*)d_out;
    (void)in_sizes; (void)n_in; (void)out_size;

    k0_twiddle<<<1, 512>>>();
    k1_rowpass<<<NPAIR, TPB>>>(x);
    k_reduce<<<1, TPB>>>();
    k2_transpose<<<dim3(FN / 32, FN / 32), dim3(32, 8)>>>();
    k3_colpass<<<FN, TPB>>>();
    k4_transpose<<<dim3(FN / 32, 8192 / 32), dim3(32, 8)>>>(out);
}

// round 5
// speedup vs baseline: 4.3169x; 1.3050x over previous
#include <cuda_runtime.h>
#include <cuda_fp16.h>
#include <cuda_bf16.h>

// FFT-based 2x upsample, fully-real polyphase formulation (see R2/R3).
// R5: fp16 intermediates (B, Bt, R) + K4 assembles output straight from Bt+R
// (the 256MB Yt2 round-trip is gone), double-buffered FFT exchanges (6 syncs).

#define FN    4096
#define TPB   512
#define NPAIR (FN / 2)
#define SMEM_FFT (2 * FN * sizeof(float2))   // 64 KB double-buffer

// B[i][j]  = half2(x[i][j], R_row_i[j])     (output cols 2j / 2j+1, row pass)
// Bt[j][i] = B[i][j]                         (transposed)
// R[c][i]  = half2(Ru, Rv')                  (odd output rows, cols 2c / 2c+1)
__device__ __align__(16) __half2 g_B [(size_t)FN * FN];
__device__ __align__(16) __half2 g_Bt[(size_t)FN * FN];
__device__ __align__(16) __half2 g_R [(size_t)FN * FN];
__device__ float g_Dpart[NPAIR];
__device__ float g_D[1];
// twA[k] = e^{-2 pi i k/4096}, twB[k] = e^{+i pi k/4096}, k < 512
__device__ __align__(16) float2 g_twA[512];
__device__ __align__(16) float2 g_twB[512];

__device__ __forceinline__ float2 cmul(float2 a, float2 b) {
    return make_float2(fmaf(a.x, b.x, -a.y * b.y), fmaf(a.x, b.y, a.y * b.x));
}
__device__ __forceinline__ float2 cadd(float2 a, float2 b) { return make_float2(a.x + b.x, a.y + b.y); }
__device__ __forceinline__ float2 csub(float2 a, float2 b) { return make_float2(a.x - b.x, a.y - b.y); }
__device__ __forceinline__ float2 cconj(float2 a) { return make_float2(a.x, -a.y); }

// Bank swizzle (see R3): bijective on [0,4096), conflict-free for all six
// exchange patterns (varying bits {0..3}, {0,1,2,6}, {3,4,5,6} per half-warp).
__device__ __forceinline__ int SW(int a) {
    return a ^ ((a >> 2) & 4) ^ ((a >> 4) & 2) ^ (((a >> 6) & 1) * 9);
}

__global__ void k0_twiddle() {
    int k = threadIdx.x;
    float sn, cs;
    sincospif(-(float)k / 2048.0f, &sn, &cs);
    g_twA[k] = make_float2(cs, sn);
    sincospif((float)k / 4096.0f, &sn, &cs);
    g_twB[k] = make_float2(cs, sn);
}

// Radix-8 DFT butterfly. FWD: W_8 = e^{-2pi i/8}; INV: conjugate.
template <bool INV>
__device__ __forceinline__ void bfly8(const float2 x[8], float2 y[8]) {
    float2 a0 = cadd(x[0], x[4]), a1 = csub(x[0], x[4]);
    float2 a2 = cadd(x[2], x[6]), a3 = csub(x[2], x[6]);
    float2 a4 = cadd(x[1], x[5]), a5 = csub(x[1], x[5]);
    float2 a6 = cadd(x[3], x[7]), a7 = csub(x[3], x[7]);
    float2 b0 = cadd(a0, a2), b1 = csub(a0, a2);
    float2 b2 = cadd(a4, a6), b3 = csub(a4, a6);
    float2 c3  = INV ? make_float2(-a3.y, a3.x) : make_float2(a3.y, -a3.x);
    float2 c7  = INV ? make_float2(-a7.y, a7.x) : make_float2(a7.y, -a7.x);
    float2 jb3 = INV ? make_float2(-b3.y, b3.x) : make_float2(b3.y, -b3.x);
    float2 e1 = cadd(a1, c3), e3 = csub(a1, c3);
    float2 f5 = cadd(a5, c7), f7 = csub(a5, c7);
    const float s = 0.70710678118654752440f;
    float2 W1 = INV ? make_float2(s, s)  : make_float2(s, -s);
    float2 W3 = INV ? make_float2(-s, s) : make_float2(-s, -s);
    float2 g5 = cmul(W1, f5), g7 = cmul(W3, f7);
    y[0] = cadd(b0, b2); y[4] = csub(b0, b2);
    y[2] = cadd(b1, jb3); y[6] = csub(b1, jb3);
    y[1] = cadd(e1, g5); y[5] = csub(e1, g5);
    y[3] = cadd(e3, g7); y[7] = csub(e3, g7);
}

__device__ __forceinline__ void twapply(float2 y[8], float2 w) {
    float2 wk = w;
    y[1] = cmul(y[1], wk);
    #pragma unroll
    for (int k = 2; k < 8; k++) { wk = cmul(wk, w); y[k] = cmul(y[k], wk); }
}

// S-transform: z <- N * IDFT( DFT(z) * halfshift_w ), zny <- DFT(z)[2048].
// Double-buffered: one __syncthreads() per exchange (6 total). Hazard-safe:
// exchange e+1's sync (after its write to the OTHER buffer) transitively
// guarantees all warps finished exchange e's reads before e+2 rewrites.
__device__ __forceinline__ void stransform(float2 z[8], float2* buf0, float2* buf1,
                                           float2* s_zny, int tid, float2* zny_out) {
    const int k0 = tid >> 6;
    const int s6 = tid & 63;
    const int k1 = (tid >> 3) & 7;
    const int n0 = tid & 7;
    const int m  = (tid >> 6) + 8 * ((tid >> 3) & 7) + 64 * (tid & 7);
    float2 y[8], t[8];

    const float2 w1b = __ldg(&g_twA[tid]);
    const float2 w2b = __ldg(&g_twA[8 * s6]);
    const float2 w3b = __ldg(&g_twA[64 * n0]);
    const float2 wm  = __ldg(&g_twB[m]);

    // ---- forward FFT ----
    bfly8<false>(z, y);
    twapply(y, w1b);
    #pragma unroll
    for (int q = 0; q < 8; q++) buf0[SW(512 * q + tid)] = y[q];
    __syncthreads();
    #pragma unroll
    for (int q = 0; q < 8; q++) t[q] = buf0[SW(512 * k0 + 64 * q + s6)];

    bfly8<false>(t, y);
    twapply(y, w2b);
    #pragma unroll
    for (int q = 0; q < 8; q++) buf1[SW(512 * k0 + 64 * q + s6)] = y[q];
    __syncthreads();
    #pragma unroll
    for (int q = 0; q < 8; q++) t[q] = buf1[SW(512 * k0 + 64 * k1 + 8 * q + n0)];

    bfly8<false>(t, y);
    twapply(y, w3b);
    #pragma unroll
    for (int q = 0; q < 8; q++) buf0[SW(512 * k0 + 64 * k1 + 8 * q + n0)] = y[q];
    __syncthreads();
    #pragma unroll
    for (int q = 0; q < 8; q++) t[q] = buf0[SW(8 * tid + q)];

    bfly8<false>(t, y);                         // -> X[m + 512 j]
    if (tid == 0) *s_zny = y[4];                // zny = X[2048]

    // ---- half-sample-shift phase (registers) ----
    {
        const float2 EJ[8] = {
            { 1.0f, 0.0f},
            { 0.92387953251128675613f,  0.38268343236508977173f},
            { 0.70710678118654752440f,  0.70710678118654752440f},
            { 0.38268343236508977173f,  0.92387953251128675613f},
            { 0.0f, -1.0f},
            { 0.38268343236508977173f, -0.92387953251128675613f},
            { 0.70710678118654752440f, -0.70710678118654752440f},
            { 0.92387953251128675613f, -0.38268343236508977173f}};
        #pragma unroll
        for (int j = 0; j < 8; j++) y[j] = cmul(y[j], cmul(wm, EJ[j]));
    }

    // ---- inverse FFT ----
    bfly8<true>(y, t);
    #pragma unroll
    for (int q = 0; q < 8; q++) buf1[SW(8 * tid + q)] = t[q];
    __syncthreads();
    #pragma unroll
    for (int q = 0; q < 8; q++) t[q] = buf1[SW(512 * k0 + 64 * k1 + 8 * q + n0)];

    twapply(t, cconj(w3b));
    bfly8<true>(t, y);
    #pragma unroll
    for (int q = 0; q < 8; q++) buf0[SW(512 * k0 + 64 * k1 + 8 * q + n0)] = y[q];
    __syncthreads();
    #pragma unroll
    for (int q = 0; q < 8; q++) t[q] = buf0[SW(512 * k0 + 64 * q + s6)];

    twapply(t, cconj(w2b));
    bfly8<true>(t, y);
    #pragma unroll
    for (int q = 0; q < 8; q++) buf1[SW(512 * k0 + 64 * q + s6)] = y[q];
    __syncthreads();
    #pragma unroll
    for (int q = 0; q < 8; q++) t[q] = buf1[SW(512 * q + tid)];

    twapply(t, cconj(w1b));
    bfly8<true>(t, z);                          // z[n3] = N*S[tid+512 n3]

    *zny_out = *s_zny;                          // >= 3 syncs after the write
}

// K1: 2-for-1 row pass (block r handles input rows 2r, 2r+1).
__global__ __launch_bounds__(TPB) void k1_rowpass(const float* __restrict__ x) {
    extern __shared__ float2 dsm[];
    __shared__ float2 s_zny;
    float2* buf0 = dsm;
    float2* buf1 = dsm + FN;
    int tid = threadIdx.x;
    size_t r = blockIdx.x;
    const float* u = x + (2 * r) * (size_t)FN;
    const float* v = u + FN;
    float2 z[8], z0[8];
    #pragma unroll
    for (int e = 0; e < 8; e++) {
        int j = tid + e * TPB;
        z[e] = make_float2(u[j], v[j]);
        z0[e] = z[e];
    }
    float2 zny;
    stransform(z, buf0, buf1, &s_zny, tid, &zny);
    if (tid == 0) g_Dpart[r] = zny.x - zny.y;

    const float invN = 1.0f / 4096.0f;
    float sgn = (tid & 1) ? -1.0f : 1.0f;       // (-1)^j
    __half2* row0 = g_B + (2 * r) * (size_t)FN;
    __half2* row1 = row0 + FN;
    #pragma unroll
    for (int e = 0; e < 8; e++) {
        int j = tid + e * TPB;
        float Ru = (z[e].x - sgn * zny.y) * invN;
        float Rv = (z[e].y + sgn * zny.x) * invN;
        row0[j] = __floats2half2_rn(z0[e].x, Ru);
        row1[j] = __floats2half2_rn(z0[e].y, Rv);
    }
}

// Deterministic reduction of g_Dpart -> g_D.
__global__ void k_reduce() {
    __shared__ float sh[TPB];
    float s = 0.0f;
    for (int i = threadIdx.x; i < NPAIR; i += TPB) s += g_Dpart[i];
    sh[threadIdx.x] = s;
    __syncthreads();
    for (int o = TPB / 2; o > 0; o >>= 1) {
        if (threadIdx.x < o) sh[threadIdx.x] += sh[threadIdx.x + o];
        __syncthreads();
    }
    if (threadIdx.x == 0) g_D[0] = sh[0];
}

// K2: transpose B [4096x4096 half2] -> Bt.
__global__ void k2_transpose() {
    __shared__ __half2 tile[32][33];
    int tx = threadIdx.x, ty = threadIdx.y;
    int cx = blockIdx.x * 32 + tx;
    int ry = blockIdx.y * 32 + ty;
    #pragma unroll
    for (int j = 0; j < 32; j += 8)
        tile[ty + j][tx] = g_B[(size_t)(ry + j) * FN + cx];
    __syncthreads();
    int ox = blockIdx.y * 32 + tx;
    int oy = blockIdx.x * 32 + ty;
    #pragma unroll
    for (int j = 0; j < 32; j += 8)
        g_Bt[(size_t)(oy + j) * FN + ox] = tile[tx][ty + j];
}

// K3: 2-for-1 column pass (block c handles output columns 2c, 2c+1).
// Writes ONLY the odd-row values: R[c][i] = (Ru, Rv + parity corr).
__global__ __launch_bounds__(TPB) void k3_colpass() {
    extern __shared__ float2 dsm[];
    __shared__ float2 s_zny;
    float2* buf0 = dsm;
    float2* buf1 = dsm + FN;
    int tid = threadIdx.x;
    size_t c = blockIdx.x;
    const __half2* bt = g_Bt + c * (size_t)FN;
    float2 z[8];
    #pragma unroll
    for (int e = 0; e < 8; e++) {
        int j = tid + e * TPB;
        z[e] = __half22float2(bt[j]);
    }
    float2 zny;
    stransform(z, buf0, buf1, &s_zny, tid, &zny);

    const float invN = 1.0f / 4096.0f;
    float corr = -g_D[0] * invN * invN;         // -D/N^2
    float sgnc = (c & 1) ? -corr : corr;        // (-1)^c * corr
    float sgn = (tid & 1) ? -1.0f : 1.0f;       // (-1)^i
    __half2* rr = g_R + c * (size_t)FN;
    #pragma unroll
    for (int e = 0; e < 8; e++) {
        int j = tid + e * TPB;
        float Ru = (z[e].x - sgn * zny.y) * invN;
        float Rv = (z[e].y + sgn * zny.x) * invN;
        rr[j] = __floats2half2_rn(Ru, Rv + sgn * sgnc);
    }
}

// K4: assemble output from Bt + R.
//   out[2i  ][2c] = Bt[c][i].lo   out[2i  ][2c+1] = Bt[c][i].hi
//   out[2i+1][2c] = R [c][i].lo   out[2i+1][2c+1] = R [c][i].hi
__global__ void k4_assemble(float* __restrict__ out) {
    __shared__ __half2 tB[32][33];
    __shared__ __half2 tR[32][33];
    int tx = threadIdx.x, ty = threadIdx.y;
    int ib = blockIdx.x * 32;
    int cb = blockIdx.y * 32;
    #pragma unroll
    for (int j = 0; j < 32; j += 8) {
        tB[ty + j][tx] = g_Bt[(size_t)(cb + ty + j) * FN + ib + tx];
        tR[ty + j][tx] = g_R [(size_t)(cb + ty + j) * FN + ib + tx];
    }
    __syncthreads();
    #pragma unroll
    for (int r8 = 0; r8 < 8; r8++) {
        int rr = ty + 8 * r8;          // 0..63 output row within block
        int i_loc = rr >> 1;
        int a = rr & 1;
        #pragma unroll
        for (int h = 0; h < 2; h++) {
            int cc = tx + 32 * h;      // 0..63 output col within block
            int c_loc = cc >> 1;
            __half2 s = a ? tR[c_loc][i_loc] : tB[c_loc][i_loc];
            float v = (cc & 1) ? __high2float(s) : __low2float(s);
            out[(size_t)(2 * (ib + i_loc) + a) * 8192 + 2 * cb + cc] = v;
        }
    }
}

extern "C" void kernel_launch(void* const* d_in, const int* in_sizes, int n_in,
                              void* d_out, int out_size) {
    const float* x = (const float*)d_in[0];
    float* out = (float*)d_out;
    (void)in_sizes; (void)n_in; (void)out_size;

    cudaFuncSetAttribute(k1_rowpass, cudaFuncAttributeMaxDynamicSharedMemorySize,
                         (int)SMEM_FFT);
    cudaFuncSetAttribute(k3_colpass, cudaFuncAttributeMaxDynamicSharedMemorySize,
                         (int)SMEM_FFT);

    k0_twiddle<<<1, 512>>>();
    k1_rowpass<<<NPAIR, TPB, SMEM_FFT>>>(x);
    k_reduce<<<1, TPB>>>();
    k2_transpose<<<dim3(FN / 32, FN / 32), dim3(32, 8)>>>();
    k3_colpass<<<FN, TPB, SMEM_FFT>>>();
    k4_assemble<<<dim3(FN / 32, FN / 32), dim3(32, 8)>>>(out);
}